// round 2
// baseline (speedup 1.0000x reference)
#include <cuda_runtime.h>
#include <cuda_bf16.h>
#include <cstdint>
#include <cstddef>

#define NB 64
#define NS 512
#define NE 128
#define NH 256
#define NG 1024      // 4*NH
#define NT 9
#define NM 32768     // NB*NS

// ---------------- scratch: device globals (no allocation allowed) -----------
__device__ float g_xz[(size_t)2 * NM * NG];      // 256 MB  input projections
__device__ float g_h [(size_t)NM * 2 * NH];      // 64 MB   concat h (fwd|bwd)
__device__ int   g_cnt[16];                      // barrier counters per group
__device__ int   g_lens[NB];

// ---------------- math helpers ----------------------------------------------
__device__ __forceinline__ float sigf(float x) { return 1.f / (1.f + __expf(-x)); }
__device__ __forceinline__ float tanhf_fast(float x) {
    float e = __expf(2.f * fabsf(x));
    float t = 1.f - 2.f / (e + 1.f);
    return copysignf(t, x);
}

// ---------------- text lens --------------------------------------------------
__global__ void k_lens(const int* __restrict__ text) {
    int b = blockIdx.x;
    int c = 0;
    for (int i = threadIdx.x; i < NS; i += 128) c += (text[b * NS + i] != 0);
    #pragma unroll
    for (int o = 16; o; o >>= 1) c += __shfl_xor_sync(0xffffffffu, c, o);
    __shared__ int ws[4];
    if ((threadIdx.x & 31) == 0) ws[threadIdx.x >> 5] = c;
    __syncthreads();
    if (threadIdx.x == 0) g_lens[b] = ws[0] + ws[1] + ws[2] + ws[3];
}

// ---------------- barrier counter reset (each replay) ------------------------
__global__ void k_reset() { if (threadIdx.x < 16) g_cnt[threadIdx.x] = 0; }

// ---------------- xz = emb[text] @ W + b  (both dirs) ------------------------
// grid (512 mtiles, 16 ntiles, 2 dirs), 256 threads, 64x64 tile, K=128
__global__ __launch_bounds__(256) void k_xz(
    const int* __restrict__ text, const float* __restrict__ emb,
    const float* __restrict__ Wf, const float* __restrict__ bf,
    const float* __restrict__ Wb, const float* __restrict__ bb)
{
    extern __shared__ float sm[];
    float* As = sm;               // 64 x 132 (pitch 132, 16B-aligned rows)
    float* Bs = sm + 64 * 132;    // 128 x 68
    __shared__ int tok[64];

    int t = threadIdx.x;
    int m0 = blockIdx.x * 64, n0 = blockIdx.y * 64, dir = blockIdx.z;
    const float* W    = dir ? Wb : Wf;
    const float* bias = dir ? bb : bf;

    if (t < 64) tok[t] = text[m0 + t];
    __syncthreads();

    // A tile: gathered emb rows (natural [m][k] layout, float4)
    #pragma unroll
    for (int i = 0; i < 8; i++) {
        int idx = t + i * 256;              // 0..2047 float4 slots
        int r = idx >> 5, c4 = idx & 31;
        float4 v = reinterpret_cast<const float4*>(emb + (size_t)tok[r] * NE)[c4];
        *reinterpret_cast<float4*>(&As[r * 132 + c4 * 4]) = v;
    }
    // B tile: W[k][n0:n0+64], natural [k][n]
    #pragma unroll
    for (int i = 0; i < 32; i++) {
        int idx = t + i * 256;
        int k = idx >> 6, n = idx & 63;
        Bs[k * 68 + n] = W[(size_t)k * NG + n0 + n];
    }
    __syncthreads();

    int tx = t & 15, ty = t >> 4;
    float acc[4][4];
    #pragma unroll
    for (int j = 0; j < 4; j++)
        #pragma unroll
        for (int i = 0; i < 4; i++) acc[j][i] = 0.f;

    #pragma unroll 4
    for (int k0 = 0; k0 < 128; k0 += 4) {
        float av[4][4];
        #pragma unroll
        for (int j = 0; j < 4; j++) {
            float4 a4 = *reinterpret_cast<const float4*>(&As[(ty * 4 + j) * 132 + k0]);
            av[j][0] = a4.x; av[j][1] = a4.y; av[j][2] = a4.z; av[j][3] = a4.w;
        }
        #pragma unroll
        for (int kk = 0; kk < 4; kk++) {
            float bv[4];
            #pragma unroll
            for (int i = 0; i < 4; i++) bv[i] = Bs[(k0 + kk) * 68 + tx + 16 * i];
            #pragma unroll
            for (int j = 0; j < 4; j++)
                #pragma unroll
                for (int i = 0; i < 4; i++) acc[j][i] += av[j][kk] * bv[i];
        }
    }

    #pragma unroll
    for (int j = 0; j < 4; j++) {
        int m = m0 + ty * 4 + j;
        size_t base = ((size_t)dir * NM + m) * NG;
        #pragma unroll
        for (int i = 0; i < 4; i++) {
            int n = n0 + tx + 16 * i;
            g_xz[base + n] = acc[j][i] + bias[n];
        }
    }
}

// ---------------- persistent LSTM --------------------------------------------
// grid (8 colblocks, 8 batch-slices, 2 dirs) = 128 blocks, 256 threads,
// 1 block/SM (149KB smem) -> all co-resident -> spin barrier is safe.
__global__ __launch_bounds__(256) void k_lstm(const float* __restrict__ Uf,
                                              const float* __restrict__ Ub)
{
    extern __shared__ float sm[];
    float* Us = sm;               // 128 x 260  (U slice, [cc][k], pitch 260)
    float* hs = sm + 128 * 260;   // 8 x 256    (current h for this batch slice)
    float* zp = hs + 8 * 256;     // 2 x 8 x 128 ([khalf][bs][cc] partials)

    const int t   = threadIdx.x;
    const int cb  = blockIdx.x, bsl = blockIdx.y, dir = blockIdx.z;
    const int j0  = cb * 32, b0 = bsl * 8;
    const int gid = dir * 8 + bsl;
    const float* U = dir ? Ub : Uf;

    // Load U slice transposed: Us[cc][k] = U[k][ (cc/32)*256 + j0 + cc%32 ]
    for (int i = t; i < 128 * 256; i += 256) {
        int cc = i & 127, k = i >> 7;
        int zc = ((cc >> 5) << 8) + j0 + (cc & 31);
        Us[cc * 260 + k] = U[(size_t)k * NG + zc];
    }
    for (int i = t; i < 8 * 256; i += 256) hs[i] = 0.f;

    // gate-phase mapping: (bs, jj)
    const int gb = t >> 5, gj = t & 31;
    // GEMM mapping: k-half, 4bs x 2cc register tile
    const int kh  = t >> 7;
    const int r   = t & 127;
    const int cc0 = r & 63;
    const int bsq = (r >> 6) * 4;
    const int kbase = kh * 128;

    float c_reg = 0.f;
    int target = 0;
    __syncthreads();

    for (int s = 0; s < NS; s++) {
        const int tm = dir ? (NS - 1 - s) : s;

        // prefetch xz for the gate phase (covered by GEMM latency)
        const float* xzp = g_xz +
            (((size_t)dir * NM + (size_t)(b0 + gb) * NS + tm) * NG + j0 + gj);
        float x0 = xzp[0], x1 = xzp[256], x2 = xzp[512], x3 = xzp[768];

        // ---- GEMM: z-partials over this thread's k-half -----------------
        float acc[8];
        #pragma unroll
        for (int q = 0; q < 8; q++) acc[q] = 0.f;
        const float* u0p = Us + cc0 * 260 + kbase;
        const float* u1p = Us + (cc0 + 64) * 260 + kbase;
        const float* hp  = hs + bsq * 256 + kbase;
        #pragma unroll 4
        for (int k = 0; k < 128; k += 4) {
            float4 u0 = *reinterpret_cast<const float4*>(u0p + k);
            float4 u1 = *reinterpret_cast<const float4*>(u1p + k);
            #pragma unroll
            for (int bi = 0; bi < 4; bi++) {
                float4 h4 = *reinterpret_cast<const float4*>(hp + bi * 256 + k);
                acc[bi * 2 + 0] += h4.x * u0.x + h4.y * u0.y + h4.z * u0.z + h4.w * u0.w;
                acc[bi * 2 + 1] += h4.x * u1.x + h4.y * u1.y + h4.z * u1.z + h4.w * u1.w;
            }
        }
        #pragma unroll
        for (int bi = 0; bi < 4; bi++) {
            zp[kh * 1024 + (bsq + bi) * 128 + cc0]      = acc[bi * 2 + 0];
            zp[kh * 1024 + (bsq + bi) * 128 + cc0 + 64] = acc[bi * 2 + 1];
        }
        __syncthreads();

        // ---- gates: thread (gb, gj) owns h/c column j0+gj of batch b0+gb
        int zb = gb * 128 + gj;
        float zi = zp[zb]      + zp[1024 + zb]      + x0;
        float zf = zp[zb + 32] + zp[1024 + zb + 32] + x1;
        float zg = zp[zb + 64] + zp[1024 + zb + 64] + x2;
        float zo = zp[zb + 96] + zp[1024 + zb + 96] + x3;
        float ig = sigf(zi), fg = sigf(zf), gg = tanhf_fast(zg), og = sigf(zo);
        c_reg = fg * c_reg + ig * gg;
        float hv = og * tanhf_fast(c_reg);
        g_h[((size_t)(b0 + gb) * NS + tm) * (2 * NH) + dir * NH + j0 + gj] = hv;
        __syncthreads();

        // ---- group barrier (8 col-blocks) --------------------------------
        target += 8;
        if (t == 0) {
            __threadfence();
            atomicAdd(&g_cnt[gid], 1);
            while (*(volatile int*)&g_cnt[gid] < target) { }
        }
        __syncthreads();

        // ---- gather full h for next step (fresh addresses -> L2 hits) ----
        if (s < NS - 1) {
            for (int i = t; i < 512; i += 256) {
                int bs = i >> 6, c4 = i & 63;
                float4 v = *reinterpret_cast<const float4*>(
                    g_h + ((size_t)(b0 + bs) * NS + tm) * (2 * NH) + dir * NH + c4 * 4);
                *reinterpret_cast<float4*>(&hs[bs * 256 + c4 * 4]) = v;
            }
            __syncthreads();
        }
    }
}

// ---------------- logits = h @ W_d + b_d -------------------------------------
__global__ __launch_bounds__(256) void k_logits(const float* __restrict__ Wd,
                                                const float* __restrict__ bd,
                                                float* __restrict__ out)
{
    __shared__ float Wd_s[512 * NT];
    __shared__ float bd_s[NT];
    int t = threadIdx.x;
    for (int i = t; i < 512 * NT; i += 256) Wd_s[i] = Wd[i];
    if (t < NT) bd_s[t] = bd[t];
    __syncthreads();

    int warp = t >> 5, lane = t & 31;
    size_t row = (size_t)blockIdx.x * 8 + warp;     // (b,t) flat, 0..32767
    const float* hr = g_h + row * (2 * NH);

    float acc[NT];
    #pragma unroll
    for (int tg = 0; tg < NT; tg++) acc[tg] = 0.f;

    #pragma unroll
    for (int i = 0; i < 4; i++) {
        int kb = i * 128 + lane * 4;
        float4 h4 = *reinterpret_cast<const float4*>(hr + kb);
        float hvv[4] = {h4.x, h4.y, h4.z, h4.w};
        #pragma unroll
        for (int w = 0; w < 4; w++) {
            int k = kb + w;
            #pragma unroll
            for (int tg = 0; tg < NT; tg++) acc[tg] += hvv[w] * Wd_s[k * NT + tg];
        }
    }
    #pragma unroll
    for (int tg = 0; tg < NT; tg++)
        #pragma unroll
        for (int o = 16; o; o >>= 1) acc[tg] += __shfl_xor_sync(0xffffffffu, acc[tg], o);
    #pragma unroll
    for (int tg = 0; tg < NT; tg++)
        if (lane == tg) out[row * NT + tg] = acc[tg] + bd_s[tg];
}

// ---------------- CRF: sequence score & log-norm -----------------------------
// one warp per batch element; reads logits from d_out
__global__ void k_crf(const int* __restrict__ labels,
                      const float* __restrict__ trans,
                      float* __restrict__ out)
{
    int b = blockIdx.x, lane = threadIdx.x;
    int len = g_lens[b];
    const float* lg = out + (size_t)b * NS * NT;
    const int*   lb = labels + (size_t)b * NS;

    // sequence score (lanes strided over t)
    float sc = 0.f;
    for (int t = lane; t < len; t += 32)     sc += lg[t * NT + lb[t]];
    for (int t = lane; t + 1 < len; t += 32) sc += trans[lb[t] * NT + lb[t + 1]];
    #pragma unroll
    for (int o = 16; o; o >>= 1) sc += __shfl_xor_sync(0xffffffffu, sc, o);

    // alpha recursion (lanes 0..8 hold alpha; all lanes join shuffles)
    bool act = lane < NT;
    float tr[NT];
    #pragma unroll
    for (int i = 0; i < NT; i++) tr[i] = act ? trans[i * NT + lane] : 0.f;
    float alpha = act ? lg[lane] : -1e30f;

    for (int t = 1; t < len; t++) {
        float lgv = act ? lg[t * NT + lane] : 0.f;
        float v[NT]; float m = -1e30f;
        #pragma unroll
        for (int i = 0; i < NT; i++) {
            float ai = __shfl_sync(0xffffffffu, alpha, i);
            v[i] = ai + tr[i];
            m = fmaxf(m, v[i]);
        }
        float s = 0.f;
        #pragma unroll
        for (int i = 0; i < NT; i++) s += expf(v[i] - m);
        float na = m + logf(s) + lgv;
        if (act) alpha = na;
    }

    // final logsumexp over tags
    float m2 = act ? alpha : -1e30f;
    #pragma unroll
    for (int o = 16; o; o >>= 1) m2 = fmaxf(m2, __shfl_xor_sync(0xffffffffu, m2, o));
    float e = act ? expf(alpha - m2) : 0.f;
    #pragma unroll
    for (int o = 16; o; o >>= 1) e += __shfl_xor_sync(0xffffffffu, e, o);
    float lognorm = m2 + logf(e);

    if (lane == 0) {
        out[(size_t)NM * NT + b]      = (float)len;     // text_lens (as f32)
        out[(size_t)NM * NT + NB + b] = sc - lognorm;   // log_likelihood
    }
}

// ---------------- launcher ----------------------------------------------------
extern "C" void kernel_launch(void* const* d_in, const int* in_sizes, int n_in,
                              void* d_out, int out_size)
{
    const int*   text   = (const int*)  d_in[0];
    const int*   labels = (const int*)  d_in[1];
    const float* emb    = (const float*)d_in[2];
    const float* Wf     = (const float*)d_in[3];
    const float* Uf     = (const float*)d_in[4];
    const float* bf     = (const float*)d_in[5];
    const float* Wb     = (const float*)d_in[6];
    const float* Ub     = (const float*)d_in[7];
    const float* bb     = (const float*)d_in[8];
    const float* Wd     = (const float*)d_in[9];
    const float* bd     = (const float*)d_in[10];
    const float* trans  = (const float*)d_in[11];
    float* out = (float*)d_out;

    const int XZ_SMEM   = (64 * 132 + 128 * 68) * 4;               // 68608 B
    const int LSTM_SMEM = (128 * 260 + 8 * 256 + 2 * 1024) * 4;    // 149504 B
    cudaFuncSetAttribute(k_xz,   cudaFuncAttributeMaxDynamicSharedMemorySize, XZ_SMEM);
    cudaFuncSetAttribute(k_lstm, cudaFuncAttributeMaxDynamicSharedMemorySize, LSTM_SMEM);

    k_lens  <<<NB, 128>>>(text);
    k_reset <<<1, 32>>>();
    k_xz    <<<dim3(512, 16, 2), 256, XZ_SMEM>>>(text, emb, Wf, bf, Wb, bb);
    k_lstm  <<<dim3(8, 8, 2), 256, LSTM_SMEM>>>(Uf, Ub);
    k_logits<<<NM / 8, 256>>>(Wd, bd, out);
    k_crf   <<<NB, 32>>>(labels, trans, out);
}

// round 3
// speedup vs baseline: 1.0869x; 1.0869x over previous
#include <cuda_runtime.h>
#include <cuda_bf16.h>
#include <cstdint>
#include <cstddef>

#define NB 64
#define NS 512
#define NE 128
#define NH 256
#define NG 1024      // 4*NH
#define NT 9
#define NM 32768     // NB*NS

// ---------------- packed fp32x2 helpers (Blackwell FFMA2 path) ---------------
#define FMA2(d, a, b) \
    asm("fma.rn.f32x2 %0, %1, %2, %0;" : "+l"(d) : "l"(a), "l"(b))
#define PACKDUP(d, x) \
    asm("mov.b64 %0, {%1, %1};" : "=l"(d) : "r"(__float_as_int(x)))
__device__ __forceinline__ float f2_lo(uint64_t v) {
    return __int_as_float((int)(v & 0xffffffffull));
}
__device__ __forceinline__ float f2_hi(uint64_t v) {
    return __int_as_float((int)(v >> 32));
}

// ---------------- scratch: device globals (no allocation allowed) -----------
__device__ float g_xz[(size_t)2 * NM * NG];      // 256 MB  input projections
__device__ float g_h [(size_t)NM * 2 * NH];      // 64 MB   concat h (fwd|bwd)
__device__ int   g_cnt[16];                      // barrier counters per group
__device__ int   g_lens[NB];

// ---------------- math helpers ----------------------------------------------
__device__ __forceinline__ float sigf(float x) { return 1.f / (1.f + __expf(-x)); }
__device__ __forceinline__ float tanhf_fast(float x) {
    float e = __expf(2.f * fabsf(x));
    float t = 1.f - 2.f / (e + 1.f);
    return copysignf(t, x);
}

// ---------------- text lens --------------------------------------------------
__global__ void k_lens(const int* __restrict__ text) {
    int b = blockIdx.x;
    int c = 0;
    for (int i = threadIdx.x; i < NS; i += 128) c += (text[b * NS + i] != 0);
    #pragma unroll
    for (int o = 16; o; o >>= 1) c += __shfl_xor_sync(0xffffffffu, c, o);
    __shared__ int ws[4];
    if ((threadIdx.x & 31) == 0) ws[threadIdx.x >> 5] = c;
    __syncthreads();
    if (threadIdx.x == 0) g_lens[b] = ws[0] + ws[1] + ws[2] + ws[3];
}

// ---------------- barrier counter reset (each replay) ------------------------
__global__ void k_reset() { if (threadIdx.x < 16) g_cnt[threadIdx.x] = 0; }

// ---------------- xz = emb[text] @ W + b  (both dirs), FFMA2 ----------------
// grid (512 mtiles, 16 ntiles, 2 dirs), 256 threads, 64x64 tile, K=128
__global__ __launch_bounds__(256) void k_xz(
    const int* __restrict__ text, const float* __restrict__ emb,
    const float* __restrict__ Wf, const float* __restrict__ bf,
    const float* __restrict__ Wb, const float* __restrict__ bb)
{
    extern __shared__ float sm[];
    float* As = sm;               // 64 x 132
    float* Bs = sm + 64 * 132;    // 128 x 68 (row stride 272B, 16B multiple)
    __shared__ int tok[64];

    int t = threadIdx.x;
    int m0 = blockIdx.x * 64, n0 = blockIdx.y * 64, dir = blockIdx.z;
    const float* W    = dir ? Wb : Wf;
    const float* bias = dir ? bb : bf;

    if (t < 64) tok[t] = text[m0 + t];
    __syncthreads();

    #pragma unroll
    for (int i = 0; i < 8; i++) {
        int idx = t + i * 256;              // 2048 float4 slots
        int r = idx >> 5, c4 = idx & 31;
        float4 v = reinterpret_cast<const float4*>(emb + (size_t)tok[r] * NE)[c4];
        *reinterpret_cast<float4*>(&As[r * 132 + c4 * 4]) = v;
    }
    #pragma unroll
    for (int i = 0; i < 32; i++) {
        int idx = t + i * 256;
        int k = idx >> 6, n = idx & 63;
        Bs[k * 68 + n] = W[(size_t)k * NG + n0 + n];
    }
    __syncthreads();

    int tx = t & 15, ty = t >> 4;           // thread tile: 4m x 4n (n contiguous)
    uint64_t acc[4][2];
    #pragma unroll
    for (int j = 0; j < 4; j++) { acc[j][0] = 0ull; acc[j][1] = 0ull; }

    #pragma unroll 4
    for (int k0 = 0; k0 < 128; k0 += 4) {
        float av[4][4];
        #pragma unroll
        for (int j = 0; j < 4; j++)
            *reinterpret_cast<float4*>(av[j]) =
                *reinterpret_cast<const float4*>(&As[(ty * 4 + j) * 132 + k0]);
        #pragma unroll
        for (int kk = 0; kk < 4; kk++) {
            ulonglong2 b2 = *reinterpret_cast<const ulonglong2*>(&Bs[(k0 + kk) * 68 + tx * 4]);
            #pragma unroll
            for (int j = 0; j < 4; j++) {
                uint64_t ad; PACKDUP(ad, av[j][kk]);
                FMA2(acc[j][0], ad, b2.x);
                FMA2(acc[j][1], ad, b2.y);
            }
        }
    }

    float4 bv = *reinterpret_cast<const float4*>(bias + n0 + tx * 4);
    #pragma unroll
    for (int j = 0; j < 4; j++) {
        int m = m0 + ty * 4 + j;
        size_t base = ((size_t)dir * NM + m) * NG + n0 + tx * 4;
        float4 o;
        o.x = f2_lo(acc[j][0]) + bv.x;
        o.y = f2_hi(acc[j][0]) + bv.y;
        o.z = f2_lo(acc[j][1]) + bv.z;
        o.w = f2_hi(acc[j][1]) + bv.w;
        *reinterpret_cast<float4*>(&g_xz[base]) = o;
    }
}

// ---------------- persistent LSTM (FFMA2 inner GEMM) -------------------------
// grid (8 colblocks, 8 batch-slices, 2 dirs) = 128 blocks, 256 threads,
// 1 block/SM (176KB smem) -> all co-resident -> spin barrier is safe.
__global__ __launch_bounds__(256) void k_lstm(const float* __restrict__ Uf,
                                              const float* __restrict__ Ub)
{
    extern __shared__ float sm[];
    float*    Us  = sm;                                // [256 k][128 cc] 128KB
    uint64_t* hsd = (uint64_t*)(sm + 32768);           // [8 bi][256 k] dup pairs 16KB
    float*    zp  = sm + 32768 + 4096;                 // [8 kq][8 bi][128 cc] 32KB

    const int t   = threadIdx.x;
    const int cb  = blockIdx.x, bsl = blockIdx.y, dir = blockIdx.z;
    const int j0  = cb * 32, b0 = bsl * 8;
    const int gid = dir * 8 + bsl;
    const float* U = dir ? Ub : Uf;

    // U slice, k-major: Us[k][cc], cc -> gate col (cc/32)*256 + j0 + cc%32
    for (int i = t; i < 128 * 256; i += 256) {
        int cc = i & 127, k = i >> 7;
        int zc = ((cc >> 5) << 8) + j0 + (cc & 31);
        Us[k * 128 + cc] = U[(size_t)k * NG + zc];
    }
    for (int i = t; i < 8 * 256; i += 256) hsd[i] = 0ull;

    // gate-phase mapping
    const int gb = t >> 5, gj = t & 31;
    // GEMM mapping: warp = k-slice (full h broadcast), lanes span cc
    const int kq = t >> 5, ccg = t & 31;
    const int kbase = kq * 32, cc0 = ccg * 4;

    float c_reg = 0.f;
    int target = 0;
    __syncthreads();

    for (int s = 0; s < NS; s++) {
        const int tm = dir ? (NS - 1 - s) : s;

        // prefetch xz for the gate phase (covered by GEMM latency)
        const float* xzp = g_xz +
            (((size_t)dir * NM + (size_t)(b0 + gb) * NS + tm) * NG + j0 + gj);
        float x0 = xzp[0], x1 = xzp[256], x2 = xzp[512], x3 = xzp[768];

        // ---- GEMM: 8 batches x 4 cc over this warp's 32-k slice ----------
        uint64_t acc[8][2];
        #pragma unroll
        for (int bi = 0; bi < 8; bi++) { acc[bi][0] = 0ull; acc[bi][1] = 0ull; }

        #pragma unroll 8
        for (int kk = 0; kk < 32; kk += 2) {
            const int k = kbase + kk;
            ulonglong2 ua = *reinterpret_cast<const ulonglong2*>(Us + k * 128 + cc0);
            ulonglong2 ub = *reinterpret_cast<const ulonglong2*>(Us + (k + 1) * 128 + cc0);
            #pragma unroll
            for (int bi = 0; bi < 8; bi++) {
                ulonglong2 hd = *reinterpret_cast<const ulonglong2*>(hsd + bi * 256 + k);
                FMA2(acc[bi][0], hd.x, ua.x);
                FMA2(acc[bi][1], hd.x, ua.y);
                FMA2(acc[bi][0], hd.y, ub.x);
                FMA2(acc[bi][1], hd.y, ub.y);
            }
        }
        #pragma unroll
        for (int bi = 0; bi < 8; bi++) {
            float4 v;
            v.x = f2_lo(acc[bi][0]); v.y = f2_hi(acc[bi][0]);
            v.z = f2_lo(acc[bi][1]); v.w = f2_hi(acc[bi][1]);
            *reinterpret_cast<float4*>(&zp[kq * 1024 + bi * 128 + cc0]) = v;
        }
        __syncthreads();

        // ---- gates: thread (gb,gj) owns col j0+gj of batch b0+gb ----------
        float zi = x0, zf = x1, zg = x2, zo = x3;
        #pragma unroll
        for (int q = 0; q < 8; q++) {
            const float* z = zp + q * 1024 + gb * 128 + gj;
            zi += z[0]; zf += z[32]; zg += z[64]; zo += z[96];
        }
        float ig = sigf(zi), fg = sigf(zf), gg = tanhf_fast(zg), og = sigf(zo);
        c_reg = fg * c_reg + ig * gg;
        float hv = og * tanhf_fast(c_reg);
        g_h[((size_t)(b0 + gb) * NS + tm) * (2 * NH) + dir * NH + j0 + gj] = hv;
        __syncthreads();

        // ---- group barrier (8 col-blocks) ---------------------------------
        target += 8;
        if (t == 0) {
            __threadfence();
            atomicAdd(&g_cnt[gid], 1);
            while (*(volatile int*)&g_cnt[gid] < target) { }
        }
        __syncthreads();

        // ---- gather full h, store duplicated pairs for FFMA2 --------------
        if (s < NS - 1) {
            for (int i = t; i < 512; i += 256) {
                int bs = i >> 6, c4 = i & 63;
                float4 v = *reinterpret_cast<const float4*>(
                    g_h + ((size_t)(b0 + bs) * NS + tm) * (2 * NH) + dir * NH + c4 * 4);
                uint64_t d0, d1, d2, d3;
                PACKDUP(d0, v.x); PACKDUP(d1, v.y); PACKDUP(d2, v.z); PACKDUP(d3, v.w);
                ulonglong2 p0; p0.x = d0; p0.y = d1;
                ulonglong2 p1; p1.x = d2; p1.y = d3;
                *reinterpret_cast<ulonglong2*>(hsd + bs * 256 + c4 * 4)     = p0;
                *reinterpret_cast<ulonglong2*>(hsd + bs * 256 + c4 * 4 + 2) = p1;
            }
            __syncthreads();
        }
    }
}

// ---------------- logits = h @ W_d + b_d -------------------------------------
__global__ __launch_bounds__(256) void k_logits(const float* __restrict__ Wd,
                                                const float* __restrict__ bd,
                                                float* __restrict__ out)
{
    __shared__ float Wd_s[512 * NT];
    __shared__ float bd_s[NT];
    int t = threadIdx.x;
    for (int i = t; i < 512 * NT; i += 256) Wd_s[i] = Wd[i];
    if (t < NT) bd_s[t] = bd[t];
    __syncthreads();

    int warp = t >> 5, lane = t & 31;
    size_t row = (size_t)blockIdx.x * 8 + warp;
    const float* hr = g_h + row * (2 * NH);

    float acc[NT];
    #pragma unroll
    for (int tg = 0; tg < NT; tg++) acc[tg] = 0.f;

    #pragma unroll
    for (int i = 0; i < 4; i++) {
        int kb = i * 128 + lane * 4;
        float4 h4 = *reinterpret_cast<const float4*>(hr + kb);
        float hvv[4] = {h4.x, h4.y, h4.z, h4.w};
        #pragma unroll
        for (int w = 0; w < 4; w++) {
            int k = kb + w;
            #pragma unroll
            for (int tg = 0; tg < NT; tg++) acc[tg] += hvv[w] * Wd_s[k * NT + tg];
        }
    }
    #pragma unroll
    for (int tg = 0; tg < NT; tg++)
        #pragma unroll
        for (int o = 16; o; o >>= 1) acc[tg] += __shfl_xor_sync(0xffffffffu, acc[tg], o);
    #pragma unroll
    for (int tg = 0; tg < NT; tg++)
        if (lane == tg) out[row * NT + tg] = acc[tg] + bd_s[tg];
}

// ---------------- CRF: sequence score & log-norm -----------------------------
__global__ void k_crf(const int* __restrict__ labels,
                      const float* __restrict__ trans,
                      float* __restrict__ out)
{
    int b = blockIdx.x, lane = threadIdx.x;
    int len = g_lens[b];
    const float* lg = out + (size_t)b * NS * NT;
    const int*   lb = labels + (size_t)b * NS;

    float sc = 0.f;
    for (int t = lane; t < len; t += 32)     sc += lg[t * NT + lb[t]];
    for (int t = lane; t + 1 < len; t += 32) sc += trans[lb[t] * NT + lb[t + 1]];
    #pragma unroll
    for (int o = 16; o; o >>= 1) sc += __shfl_xor_sync(0xffffffffu, sc, o);

    bool act = lane < NT;
    float tr[NT];
    #pragma unroll
    for (int i = 0; i < NT; i++) tr[i] = act ? trans[i * NT + lane] : 0.f;
    float alpha = act ? lg[lane] : -1e30f;

    for (int t = 1; t < len; t++) {
        float lgv = act ? lg[t * NT + lane] : 0.f;
        float v[NT]; float m = -1e30f;
        #pragma unroll
        for (int i = 0; i < NT; i++) {
            float ai = __shfl_sync(0xffffffffu, alpha, i);
            v[i] = ai + tr[i];
            m = fmaxf(m, v[i]);
        }
        float ssum = 0.f;
        #pragma unroll
        for (int i = 0; i < NT; i++) ssum += expf(v[i] - m);
        float na = m + logf(ssum) + lgv;
        if (act) alpha = na;
    }

    float m2 = act ? alpha : -1e30f;
    #pragma unroll
    for (int o = 16; o; o >>= 1) m2 = fmaxf(m2, __shfl_xor_sync(0xffffffffu, m2, o));
    float e = act ? expf(alpha - m2) : 0.f;
    #pragma unroll
    for (int o = 16; o; o >>= 1) e += __shfl_xor_sync(0xffffffffu, e, o);
    float lognorm = m2 + logf(e);

    if (lane == 0) {
        out[(size_t)NM * NT + b]      = (float)len;
        out[(size_t)NM * NT + NB + b] = sc - lognorm;
    }
}

// ---------------- launcher ----------------------------------------------------
extern "C" void kernel_launch(void* const* d_in, const int* in_sizes, int n_in,
                              void* d_out, int out_size)
{
    const int*   text   = (const int*)  d_in[0];
    const int*   labels = (const int*)  d_in[1];
    const float* emb    = (const float*)d_in[2];
    const float* Wf     = (const float*)d_in[3];
    const float* Uf     = (const float*)d_in[4];
    const float* bf     = (const float*)d_in[5];
    const float* Wb     = (const float*)d_in[6];
    const float* Ub     = (const float*)d_in[7];
    const float* bb     = (const float*)d_in[8];
    const float* Wd     = (const float*)d_in[9];
    const float* bd     = (const float*)d_in[10];
    const float* trans  = (const float*)d_in[11];
    float* out = (float*)d_out;

    const int XZ_SMEM   = (64 * 132 + 128 * 68) * 4;           // 68608 B
    const int LSTM_SMEM = (32768 + 4096 + 8192) * 4;           // 180224 B
    cudaFuncSetAttribute(k_xz,   cudaFuncAttributeMaxDynamicSharedMemorySize, XZ_SMEM);
    cudaFuncSetAttribute(k_lstm, cudaFuncAttributeMaxDynamicSharedMemorySize, LSTM_SMEM);

    k_lens  <<<NB, 128>>>(text);
    k_reset <<<1, 32>>>();
    k_xz    <<<dim3(512, 16, 2), 256, XZ_SMEM>>>(text, emb, Wf, bf, Wb, bb);
    k_lstm  <<<dim3(8, 8, 2), 256, LSTM_SMEM>>>(Uf, Ub);
    k_logits<<<NM / 8, 256>>>(Wd, bd, out);
    k_crf   <<<NB, 32>>>(labels, trans, out);
}